// round 4
// baseline (speedup 1.0000x reference)
#include <cuda_runtime.h>
#include <cstdint>

#define BB 8
#define LL 256
#define DD 512
#define HH 512
#define NTOT (LL*BB*LL)          // 524288

// Scratch: transposed projections dl_t[b][h][i], dr_t[b][h][i]
__device__ float g_dlt[BB*HH*LL];
__device__ float g_drt[BB*HH*LL];
__device__ int   g_done[BB];     // per-batch completed GEMM tile count (32 = ready)

// ---------------------------------------------------------------------------
// f32x2 packed-math helpers (Blackwell FFMA2 / FADD2 — only reachable via PTX)
// ---------------------------------------------------------------------------
typedef unsigned long long u64;

__device__ __forceinline__ u64 pack2(float lo, float hi) {
    u64 r; asm("mov.b64 %0, {%1, %2};" : "=l"(r) : "f"(lo), "f"(hi)); return r;
}
__device__ __forceinline__ void unpack2(u64 v, float& lo, float& hi) {
    asm("mov.b64 {%0, %1}, %2;" : "=f"(lo), "=f"(hi) : "l"(v));
}
__device__ __forceinline__ u64 add2(u64 a, u64 b) {
    u64 r; asm("add.rn.f32x2 %0, %1, %2;" : "=l"(r) : "l"(a), "l"(b)); return r;
}
__device__ __forceinline__ void ffma2(u64& d, u64 a, u64 b) {
    asm("fma.rn.f32x2 %0, %1, %2, %0;" : "+l"(d) : "l"(a), "l"(b));
}

// ---------------------------------------------------------------------------
// Threefry2x32, key (0, 42), partitionable path: counter = (0, m),
// output bits = lane0 ^ lane1.
// ---------------------------------------------------------------------------
__device__ __forceinline__ unsigned threefry_bits_partitionable(unsigned m)
{
    const unsigned k0 = 0u, k1 = 42u;
    const unsigned k2 = 0x1BD11BDAu ^ k0 ^ k1;
    unsigned x0 = 0u + k0;
    unsigned x1 = m  + k1;
#define TF_RND(r) { x0 += x1; x1 = __funnelshift_l(x1, x1, r); x1 ^= x0; }
    TF_RND(13) TF_RND(15) TF_RND(26) TF_RND(6)   x0 += k1; x1 += k2 + 1u;
    TF_RND(17) TF_RND(29) TF_RND(16) TF_RND(24)  x0 += k2; x1 += k0 + 2u;
    TF_RND(13) TF_RND(15) TF_RND(26) TF_RND(6)   x0 += k0; x1 += k1 + 3u;
    TF_RND(17) TF_RND(29) TF_RND(16) TF_RND(24)  x0 += k1; x1 += k2 + 4u;
    TF_RND(13) TF_RND(15) TF_RND(26) TF_RND(6)   x0 += k2; x1 += k0 + 5u;
#undef TF_RND
    return x0 ^ x1;
}

__device__ __forceinline__ float tanh_fast(float x)
{
    float y;
    asm("tanh.approx.f32 %0, %1;" : "=f"(y) : "f"(x));
    return y;
}

// ---------------------------------------------------------------------------
// Reset per-batch flags (runs first each call -> deterministic replays)
// ---------------------------------------------------------------------------
__global__ void reset_kernel()
{
    if (threadIdx.x < BB) g_done[threadIdx.x] = 0;
}

// ---------------------------------------------------------------------------
// Fused persistent kernel.
//   CTAs [0,148)    : GEMM producers. 256 tiles (64h x 64i per b), grid-stride.
//   CTAs [148,296)  : biaffine consumers. 256 tiles (64i x 32j per b),
//                     spin on g_done[b]==32 before consuming batch b.
// One producer + one consumer co-resident per SM -> FFMA pipe (GEMM) and
// MUFU pipe (tanh) run concurrently.
// ---------------------------------------------------------------------------
__global__ __launch_bounds__(256) void fused_kernel(
    const float* __restrict__ enc,
    const float* __restrict__ Wl,
    const float* __restrict__ Wr,
    const float* __restrict__ U,
    const float* __restrict__ logit_bias,
    float* __restrict__ out)
{
    __shared__ union {
        struct { float se[16][68]; float swl[16][64]; float swr[16][64]; } p;
        struct { float sl[32][64]; float sr[32][32]; float su[32]; } c;
    } sm;

    const int bid = blockIdx.x;
    const int tid = threadIdx.x;

    if (bid < 148) {
        // =================== PRODUCER: dual GEMM ===========================
        const int tx = tid & 15;      // h group (4 h each)
        const int ty = tid >> 4;      // i group (4 i each)

        for (int t = bid; t < 256; t += 148) {
            const int b  = t >> 5;
            const int r  = t & 31;
            const int h0 = (r >> 2) << 6;
            const int i0 = (r & 3) << 6;

            u64 accl2[4][2], accr2[4][2];
#pragma unroll
            for (int a = 0; a < 4; a++)
#pragma unroll
                for (int c2 = 0; c2 < 2; c2++) { accl2[a][c2] = 0ull; accr2[a][c2] = 0ull; }

            for (int k0 = 0; k0 < DD; k0 += 16) {
                {
                    int kk = tid >> 4;          // 0..15
                    int hh = (tid & 15) << 2;   // 0..60
                    const float4 vl = *(const float4*)&Wl[(k0 + kk) * HH + h0 + hh];
                    const float4 vr = *(const float4*)&Wr[(k0 + kk) * HH + h0 + hh];
                    *(float4*)&sm.p.swl[kk][hh] = vl;
                    *(float4*)&sm.p.swr[kk][hh] = vr;
                }
                {
                    int ii = tid >> 2;          // 0..63
                    int kk = (tid & 3) << 2;    // 0,4,8,12
                    const float4 v = *(const float4*)&enc[(b * LL + i0 + ii) * DD + k0 + kk];
                    sm.p.se[kk + 0][ii] = v.x;
                    sm.p.se[kk + 1][ii] = v.y;
                    sm.p.se[kk + 2][ii] = v.z;
                    sm.p.se[kk + 3][ii] = v.w;
                }
                __syncthreads();

#pragma unroll
                for (int kk = 0; kk < 16; kk++) {
                    float ev[4];
                    *(float4*)ev = *(const float4*)&sm.p.se[kk][ty << 2];
                    const u64 wl01 = *(const u64*)&sm.p.swl[kk][tx << 2];
                    const u64 wl23 = *(const u64*)&sm.p.swl[kk][(tx << 2) + 2];
                    const u64 wr01 = *(const u64*)&sm.p.swr[kk][tx << 2];
                    const u64 wr23 = *(const u64*)&sm.p.swr[kk][(tx << 2) + 2];
#pragma unroll
                    for (int a = 0; a < 4; a++) {
                        const u64 ea = pack2(ev[a], ev[a]);
                        ffma2(accl2[a][0], ea, wl01);
                        ffma2(accl2[a][1], ea, wl23);
                        ffma2(accr2[a][0], ea, wr01);
                        ffma2(accr2[a][1], ea, wr23);
                    }
                }
                __syncthreads();
            }

            // store dl_t/dr_t: [b][h][i]
#pragma unroll
            for (int c2 = 0; c2 < 2; c2++) {
                float l0[4], l1[4], r0[4], r1[4];
#pragma unroll
                for (int a = 0; a < 4; a++) {
                    unpack2(accl2[a][c2], l0[a], l1[a]);
                    unpack2(accr2[a][c2], r0[a], r1[a]);
                }
                const int h    = h0 + (tx << 2) + (c2 << 1);
                const int base = (b * HH + h) * LL + i0 + (ty << 2);
                *(float4*)&g_dlt[base]      = make_float4(l0[0], l0[1], l0[2], l0[3]);
                *(float4*)&g_dlt[base + LL] = make_float4(l1[0], l1[1], l1[2], l1[3]);
                *(float4*)&g_drt[base]      = make_float4(r0[0], r0[1], r0[2], r0[3]);
                *(float4*)&g_drt[base + LL] = make_float4(r1[0], r1[1], r1[2], r1[3]);
            }

            __syncthreads();               // all stores of this tile issued
            __threadfence();               // make them visible device-wide
            if (tid == 0) atomicAdd(&g_done[b], 1);
        }
    } else {
        // =================== CONSUMER: biaffine + epilogue =================
        const int tx = tid & 15;      // j group (2 j each)
        const int ty = tid >> 4;      // i group (4 i each)

        for (int t = bid - 148; t < 256; t += 148) {
            const int b  = t >> 5;
            const int r  = t & 31;
            const int j0 = (r >> 2) << 5;
            const int i0 = (r & 3) << 6;

            // wait for batch b's projections
            if (tid == 0) {
                while (((volatile int*)g_done)[b] < 32) __nanosleep(128);
            }
            __syncthreads();
            __threadfence();

            u64 acc2[4];
#pragma unroll
            for (int a = 0; a < 4; a++) acc2[a] = 0ull;

            for (int h0k = 0; h0k < HH; h0k += 32) {
#pragma unroll
                for (int q = 0; q < 2; q++) {
                    int idx = tid + q * 256;        // 0..511
                    int hk  = idx >> 4;             // 0..31
                    int col = (idx & 15) << 2;      // 0..60
                    *(float4*)&sm.c.sl[hk][col] =
                        *(const float4*)&g_dlt[(b * HH + h0k + hk) * LL + i0 + col];
                }
                {
                    int hk  = tid >> 3;             // 0..31
                    int col = (tid & 7) << 2;       // 0..28
                    *(float4*)&sm.c.sr[hk][col] =
                        *(const float4*)&g_drt[(b * HH + h0k + hk) * LL + j0 + col];
                }
                if (tid < 32) sm.c.su[tid] = U[h0k + tid];
                __syncthreads();

#pragma unroll
                for (int hk = 0; hk < 32; hk++) {
                    float dl[4];
                    *(float4*)dl = *(const float4*)&sm.c.sl[hk][ty << 2];
                    const u64 dr2 = *(const u64*)&sm.c.sr[hk][tx << 1];
                    const float u = sm.c.su[hk];
                    const u64 uu  = pack2(u, u);
#pragma unroll
                    for (int a = 0; a < 4; a++) {
                        const u64 x2 = add2(pack2(dl[a], dl[a]), dr2);
                        float x0, x1;
                        unpack2(x2, x0, x1);
                        const float t0 = tanh_fast(x0);
                        const float t1 = tanh_fast(x1);
                        ffma2(acc2[a], uu, pack2(t0, t1));
                    }
                }
                __syncthreads();
            }

            const float lb = logit_bias[0];

#pragma unroll
            for (int a = 0; a < 4; a++) {
                float av[2];
                unpack2(acc2[a], av[0], av[1]);
#pragma unroll
                for (int c = 0; c < 2; c++) {
                    const int i = i0 + (ty << 2) + a;
                    const int j = j0 + (tx << 1) + c;
                    float x = av[c] + lb;
                    if (i == j) x -= 1e8f;

                    const int m = i * (BB * LL) + b * LL + j;   // [L,B,L] flat

                    // mask_scores
                    out[NTOT + m] = x;

                    // p = sigmoid(x)
                    const float p = 1.0f / (1.0f + expf(-x));

                    // entropy = p*softplus(-x) + (1-p)*softplus(x)
                    const float e  = expf(-fabsf(x));
                    const float l1 = log1pf(e);
                    const float sp_pos = fmaxf(x, 0.f) + l1;
                    const float sp_neg = fmaxf(-x, 0.f) + l1;
                    out[2 * NTOT + m] = p * sp_neg + (1.0f - p) * sp_pos;

                    // bernoulli sample, JAX partitionable threefry (key=42)
                    const unsigned bits = threefry_bits_partitionable((unsigned)m);
                    const float u01 = __uint_as_float((bits >> 9) | 0x3f800000u) - 1.0f;
                    out[m] = (u01 < p) ? 1.0f : 0.0f;
                }
            }
            __syncthreads();   // protect smem before next tile's loads
        }
    }
}

// ---------------------------------------------------------------------------
extern "C" void kernel_launch(void* const* d_in, const int* in_sizes, int n_in,
                              void* d_out, int out_size)
{
    const float* enc  = (const float*)d_in[0];
    const float* Wl   = (const float*)d_in[1];
    const float* Wr   = (const float*)d_in[2];
    const float* U    = (const float*)d_in[3];
    const float* bias = (const float*)d_in[4];
    float* out = (float*)d_out;

    reset_kernel<<<1, 32>>>();
    fused_kernel<<<296, 256>>>(enc, Wl, Wr, U, bias, out);
}

// round 5
// speedup vs baseline: 1.8613x; 1.8613x over previous
#include <cuda_runtime.h>
#include <cstdint>

#define BB 8
#define LL 256
#define DD 512
#define HH 512
#define NTOT (LL*BB*LL)          // 524288

// Scratch: transposed projections dl_t[b][h][i], dr_t[b][h][i]
__device__ float g_dlt[BB*HH*LL];
__device__ float g_drt[BB*HH*LL];

// ---------------------------------------------------------------------------
// f32x2 packed-math helpers (Blackwell FFMA2 — only reachable via PTX)
// ---------------------------------------------------------------------------
typedef unsigned long long u64;

__device__ __forceinline__ u64 pack2(float lo, float hi) {
    u64 r; asm("mov.b64 %0, {%1, %2};" : "=l"(r) : "f"(lo), "f"(hi)); return r;
}
__device__ __forceinline__ void unpack2(u64 v, float& lo, float& hi) {
    asm("mov.b64 {%0, %1}, %2;" : "=f"(lo), "=f"(hi) : "l"(v));
}
__device__ __forceinline__ void ffma2(u64& d, u64 a, u64 b) {
    asm("fma.rn.f32x2 %0, %1, %2, %0;" : "+l"(d) : "l"(a), "l"(b));
}

// ---------------------------------------------------------------------------
// Kernel 1: fused dual GEMM with packed f32x2 FMAs.
//   dl_t[b,h,i] = sum_k enc[b,i,k]*Wl[k,h];  dr_t likewise with Wr.
// Block: 64h x 64i tile for one b. 256 threads, per thread 4i x 4h (x2 L/R),
// accumulated as 4i x 2 h-pairs of f32x2.
// ---------------------------------------------------------------------------
__global__ __launch_bounds__(256) void dual_gemm_kernel(
    const float* __restrict__ enc,
    const float* __restrict__ Wl,
    const float* __restrict__ Wr)
{
    const int b  = blockIdx.z;
    const int h0 = blockIdx.x * 64;
    const int i0 = blockIdx.y * 64;

    __shared__ float se[16][68];   // [k][i] (padded)
    __shared__ float swl[16][64];  // [k][h]
    __shared__ float swr[16][64];

    const int tid = threadIdx.x;
    const int tx  = tid & 15;      // h group (4 h each)
    const int ty  = tid >> 4;      // i group (4 i each)

    u64 accl2[4][2], accr2[4][2];  // [a=i][h-pair]
#pragma unroll
    for (int a = 0; a < 4; a++)
#pragma unroll
        for (int c2 = 0; c2 < 2; c2++) { accl2[a][c2] = 0ull; accr2[a][c2] = 0ull; }

    for (int k0 = 0; k0 < DD; k0 += 16) {
        {
            int kk = tid >> 4;          // 0..15
            int hh = (tid & 15) << 2;   // 0..60
            const float4 vl = *(const float4*)&Wl[(k0 + kk) * HH + h0 + hh];
            const float4 vr = *(const float4*)&Wr[(k0 + kk) * HH + h0 + hh];
            *(float4*)&swl[kk][hh] = vl;
            *(float4*)&swr[kk][hh] = vr;
        }
        {
            int ii = tid >> 2;          // 0..63
            int kk = (tid & 3) << 2;    // 0,4,8,12
            const float4 v = *(const float4*)&enc[(b * LL + i0 + ii) * DD + k0 + kk];
            se[kk + 0][ii] = v.x;
            se[kk + 1][ii] = v.y;
            se[kk + 2][ii] = v.z;
            se[kk + 3][ii] = v.w;
        }
        __syncthreads();

#pragma unroll
        for (int kk = 0; kk < 16; kk++) {
            float ev[4];
            *(float4*)ev = *(const float4*)&se[kk][ty << 2];
            const u64 wl01 = *(const u64*)&swl[kk][tx << 2];
            const u64 wl23 = *(const u64*)&swl[kk][(tx << 2) + 2];
            const u64 wr01 = *(const u64*)&swr[kk][tx << 2];
            const u64 wr23 = *(const u64*)&swr[kk][(tx << 2) + 2];
#pragma unroll
            for (int a = 0; a < 4; a++) {
                const u64 ea = pack2(ev[a], ev[a]);
                ffma2(accl2[a][0], ea, wl01);
                ffma2(accl2[a][1], ea, wl23);
                ffma2(accr2[a][0], ea, wr01);
                ffma2(accr2[a][1], ea, wr23);
            }
        }
        __syncthreads();
    }

    // store dl_t/dr_t: [b][h][i]
#pragma unroll
    for (int c2 = 0; c2 < 2; c2++) {
        float l0[4], l1[4], r0[4], r1[4];
#pragma unroll
        for (int a = 0; a < 4; a++) {
            unpack2(accl2[a][c2], l0[a], l1[a]);
            unpack2(accr2[a][c2], r0[a], r1[a]);
        }
        const int h    = h0 + (tx << 2) + (c2 << 1);
        const int base = (b * HH + h) * LL + i0 + (ty << 2);
        *(float4*)&g_dlt[base]      = make_float4(l0[0], l0[1], l0[2], l0[3]);
        *(float4*)&g_dlt[base + LL] = make_float4(l1[0], l1[1], l1[2], l1[3]);
        *(float4*)&g_drt[base]      = make_float4(r0[0], r0[1], r0[2], r0[3]);
        *(float4*)&g_drt[base + LL] = make_float4(r1[0], r1[1], r1[2], r1[3]);
    }
}

// ---------------------------------------------------------------------------
// Threefry2x32, key (0, 42), partitionable path: counter = (0, m),
// output bits = lane0 ^ lane1.
// ---------------------------------------------------------------------------
__device__ __forceinline__ unsigned threefry_bits_partitionable(unsigned m)
{
    const unsigned k0 = 0u, k1 = 42u;
    const unsigned k2 = 0x1BD11BDAu ^ k0 ^ k1;
    unsigned x0 = 0u + k0;
    unsigned x1 = m  + k1;
#define TF_RND(r) { x0 += x1; x1 = __funnelshift_l(x1, x1, r); x1 ^= x0; }
    TF_RND(13) TF_RND(15) TF_RND(26) TF_RND(6)   x0 += k1; x1 += k2 + 1u;
    TF_RND(17) TF_RND(29) TF_RND(16) TF_RND(24)  x0 += k2; x1 += k0 + 2u;
    TF_RND(13) TF_RND(15) TF_RND(26) TF_RND(6)   x0 += k0; x1 += k1 + 3u;
    TF_RND(17) TF_RND(29) TF_RND(16) TF_RND(24)  x0 += k1; x1 += k2 + 4u;
    TF_RND(13) TF_RND(15) TF_RND(26) TF_RND(6)   x0 += k2; x1 += k0 + 5u;
#undef TF_RND
    return x0 ^ x1;
}

__device__ __forceinline__ float tanh_fast(float x)
{
    float y;
    asm("tanh.approx.f32 %0, %1;" : "=f"(y) : "f"(x));
    return y;
}

// ---------------------------------------------------------------------------
// Kernel 2: biaffine + epilogue. 64i x 32j tile per CTA -> 256 CTAs.
// 256 threads, 4i x 2j per thread. (round-3 version, MUFU-bound)
// ---------------------------------------------------------------------------
__global__ __launch_bounds__(256) void biaffine_kernel(
    const float* __restrict__ U,
    const float* __restrict__ logit_bias,
    float* __restrict__ out)
{
    const int b  = blockIdx.z;
    const int i0 = blockIdx.y * 64;
    const int j0 = blockIdx.x * 32;

    __shared__ float sl[32][64];   // [h][i]
    __shared__ float sr[32][32];   // [h][j]
    __shared__ float su[32];

    const int tid = threadIdx.x;
    const int tx  = tid & 15;      // j group (2 j each)
    const int ty  = tid >> 4;      // i group (4 i each)

    float acc[4][2];               // [a=i][c=j]
#pragma unroll
    for (int a = 0; a < 4; a++)
#pragma unroll
        for (int c = 0; c < 2; c++) acc[a][c] = 0.f;

    for (int h0 = 0; h0 < HH; h0 += 32) {
#pragma unroll
        for (int q = 0; q < 2; q++) {
            int idx = tid + q * 256;        // 0..511
            int hk  = idx >> 4;             // 0..31
            int col = (idx & 15) << 2;      // 0..60
            *(float4*)&sl[hk][col] = *(const float4*)&g_dlt[(b * HH + h0 + hk) * LL + i0 + col];
        }
        {
            int hk  = tid >> 3;             // 0..31
            int col = (tid & 7) << 2;       // 0..28
            *(float4*)&sr[hk][col] = *(const float4*)&g_drt[(b * HH + h0 + hk) * LL + j0 + col];
        }
        if (tid < 32) su[tid] = U[h0 + tid];
        __syncthreads();

#pragma unroll
        for (int hk = 0; hk < 32; hk++) {
            float dl[4], dr[2];
            *(float4*)dl = *(const float4*)&sl[hk][ty << 2];
            *(float2*)dr = *(const float2*)&sr[hk][tx << 1];
            const float u = su[hk];
#pragma unroll
            for (int a = 0; a < 4; a++)
#pragma unroll
                for (int c = 0; c < 2; c++)
                    acc[a][c] = fmaf(u, tanh_fast(dl[a] + dr[c]), acc[a][c]);
        }
        __syncthreads();
    }

    const float lb = logit_bias[0];

#pragma unroll
    for (int a = 0; a < 4; a++) {
#pragma unroll
        for (int c = 0; c < 2; c++) {
            const int i = i0 + (ty << 2) + a;
            const int j = j0 + (tx << 1) + c;
            float x = acc[a][c] + lb;
            if (i == j) x -= 1e8f;

            const int m = i * (BB * LL) + b * LL + j;   // [L,B,L] flat index

            // mask_scores
            out[NTOT + m] = x;

            // p = sigmoid(x)
            const float p = 1.0f / (1.0f + expf(-x));

            // entropy = p*softplus(-x) + (1-p)*softplus(x)
            const float e  = expf(-fabsf(x));
            const float l1 = log1pf(e);
            const float sp_pos = fmaxf(x, 0.f) + l1;   // softplus(x)
            const float sp_neg = fmaxf(-x, 0.f) + l1;  // softplus(-x)
            out[2 * NTOT + m] = p * sp_neg + (1.0f - p) * sp_pos;

            // bernoulli sample, JAX partitionable threefry (key=42)
            const unsigned bits = threefry_bits_partitionable((unsigned)m);
            const float u01 = __uint_as_float((bits >> 9) | 0x3f800000u) - 1.0f;
            out[m] = (u01 < p) ? 1.0f : 0.0f;
        }
    }
}

// ---------------------------------------------------------------------------
extern "C" void kernel_launch(void* const* d_in, const int* in_sizes, int n_in,
                              void* d_out, int out_size)
{
    const float* enc  = (const float*)d_in[0];
    const float* Wl   = (const float*)d_in[1];
    const float* Wr   = (const float*)d_in[2];
    const float* U    = (const float*)d_in[3];
    const float* bias = (const float*)d_in[4];
    float* out = (float*)d_out;

    dim3 g1(HH / 64, LL / 64, BB);   // 8 x 4 x 8 = 256 CTAs
    dual_gemm_kernel<<<g1, 256>>>(enc, Wl, Wr);

    dim3 g2(LL / 32, LL / 64, BB);   // 8 x 4 x 8 = 256 CTAs
    biaffine_kernel<<<g2, 256>>>(U, bias, out);
}

// round 7
// speedup vs baseline: 1.9827x; 1.0652x over previous
#include <cuda_runtime.h>
#include <cstdint>

#define BB 8
#define LL 256
#define DD 512
#define HH 512
#define NTOT (LL*BB*LL)          // 524288

// Scratch: transposed projections dl_t[b][h][i], dr_t[b][h][i]
__device__ float g_dlt[BB*HH*LL];
__device__ float g_drt[BB*HH*LL];

// ---------------------------------------------------------------------------
// f32x2 packed-math helpers
// ---------------------------------------------------------------------------
typedef unsigned long long u64;

__device__ __forceinline__ u64 pack2(float lo, float hi) {
    u64 r; asm("mov.b64 %0, {%1, %2};" : "=l"(r) : "f"(lo), "f"(hi)); return r;
}
__device__ __forceinline__ void unpack2(u64 v, float& lo, float& hi) {
    asm("mov.b64 {%0, %1}, %2;" : "=f"(lo), "=f"(hi) : "l"(v));
}
__device__ __forceinline__ void ffma2(u64& d, u64 a, u64 b) {
    asm("fma.rn.f32x2 %0, %1, %2, %0;" : "+l"(d) : "l"(a), "l"(b));
}

// ---------------------------------------------------------------------------
// Kernel 1: fused dual GEMM (round-5 version, at FFMA floor).
// Block: 64h x 64i tile for one b. 256 threads.
// ---------------------------------------------------------------------------
__global__ __launch_bounds__(256) void dual_gemm_kernel(
    const float* __restrict__ enc,
    const float* __restrict__ Wl,
    const float* __restrict__ Wr)
{
    const int b  = blockIdx.z;
    const int h0 = blockIdx.x * 64;
    const int i0 = blockIdx.y * 64;

    __shared__ float se[16][68];   // [k][i] (padded)
    __shared__ float swl[16][64];  // [k][h]
    __shared__ float swr[16][64];

    const int tid = threadIdx.x;
    const int tx  = tid & 15;      // h group (4 h each)
    const int ty  = tid >> 4;      // i group (4 i each)

    u64 accl2[4][2], accr2[4][2];  // [a=i][h-pair]
#pragma unroll
    for (int a = 0; a < 4; a++)
#pragma unroll
        for (int c2 = 0; c2 < 2; c2++) { accl2[a][c2] = 0ull; accr2[a][c2] = 0ull; }

    for (int k0 = 0; k0 < DD; k0 += 16) {
        {
            int kk = tid >> 4;          // 0..15
            int hh = (tid & 15) << 2;   // 0..60
            const float4 vl = *(const float4*)&Wl[(k0 + kk) * HH + h0 + hh];
            const float4 vr = *(const float4*)&Wr[(k0 + kk) * HH + h0 + hh];
            *(float4*)&swl[kk][hh] = vl;
            *(float4*)&swr[kk][hh] = vr;
        }
        {
            int ii = tid >> 2;          // 0..63
            int kk = (tid & 3) << 2;    // 0,4,8,12
            const float4 v = *(const float4*)&enc[(b * LL + i0 + ii) * DD + k0 + kk];
            se[kk + 0][ii] = v.x;
            se[kk + 1][ii] = v.y;
            se[kk + 2][ii] = v.z;
            se[kk + 3][ii] = v.w;
        }
        __syncthreads();

#pragma unroll
        for (int kk = 0; kk < 16; kk++) {
            float ev[4];
            *(float4*)ev = *(const float4*)&se[kk][ty << 2];
            const u64 wl01 = *(const u64*)&swl[kk][tx << 2];
            const u64 wl23 = *(const u64*)&swl[kk][(tx << 2) + 2];
            const u64 wr01 = *(const u64*)&swr[kk][tx << 2];
            const u64 wr23 = *(const u64*)&swr[kk][(tx << 2) + 2];
#pragma unroll
            for (int a = 0; a < 4; a++) {
                const u64 ea = pack2(ev[a], ev[a]);
                ffma2(accl2[a][0], ea, wl01);
                ffma2(accl2[a][1], ea, wl23);
                ffma2(accr2[a][0], ea, wr01);
                ffma2(accr2[a][1], ea, wr23);
            }
        }
        __syncthreads();
    }

#pragma unroll
    for (int c2 = 0; c2 < 2; c2++) {
        float l0[4], l1[4], r0[4], r1[4];
#pragma unroll
        for (int a = 0; a < 4; a++) {
            unpack2(accl2[a][c2], l0[a], l1[a]);
            unpack2(accr2[a][c2], r0[a], r1[a]);
        }
        const int h    = h0 + (tx << 2) + (c2 << 1);
        const int base = (b * HH + h) * LL + i0 + (ty << 2);
        *(float4*)&g_dlt[base]      = make_float4(l0[0], l0[1], l0[2], l0[3]);
        *(float4*)&g_dlt[base + LL] = make_float4(l1[0], l1[1], l1[2], l1[3]);
        *(float4*)&g_drt[base]      = make_float4(r0[0], r0[1], r0[2], r0[3]);
        *(float4*)&g_drt[base + LL] = make_float4(r1[0], r1[1], r1[2], r1[3]);
    }
}

// ---------------------------------------------------------------------------
// Threefry2x32, key (0, 42), partitionable path: counter = (0, m),
// output bits = lane0 ^ lane1.
// ---------------------------------------------------------------------------
__device__ __forceinline__ unsigned threefry_bits_partitionable(unsigned m)
{
    const unsigned k0 = 0u, k1 = 42u;
    const unsigned k2 = 0x1BD11BDAu ^ k0 ^ k1;
    unsigned x0 = 0u + k0;
    unsigned x1 = m  + k1;
#define TF_RND(r) { x0 += x1; x1 = __funnelshift_l(x1, x1, r); x1 ^= x0; }
    TF_RND(13) TF_RND(15) TF_RND(26) TF_RND(6)   x0 += k1; x1 += k2 + 1u;
    TF_RND(17) TF_RND(29) TF_RND(16) TF_RND(24)  x0 += k2; x1 += k0 + 2u;
    TF_RND(13) TF_RND(15) TF_RND(26) TF_RND(6)   x0 += k0; x1 += k1 + 3u;
    TF_RND(17) TF_RND(29) TF_RND(16) TF_RND(24)  x0 += k1; x1 += k2 + 4u;
    TF_RND(13) TF_RND(15) TF_RND(26) TF_RND(6)   x0 += k2; x1 += k0 + 5u;
#undef TF_RND
    return x0 ^ x1;
}

__device__ __forceinline__ float tanh_fast(float x)
{
    float y;
    asm("tanh.approx.f32 %0, %1;" : "=f"(y) : "f"(x));
    return y;
}

// ---------------------------------------------------------------------------
// Kernel 2: biaffine + epilogue. 32i x 16j tile per CTA -> 1024 CTAs
// (6-8 resident CTAs/SM -> MUFU pipe actually saturated).
// 256 threads: tx (0-15) = j, ty (0-15) = i group of 2. acc[2].
// Accumulation order over h identical to the passing round-5 kernel.
// ---------------------------------------------------------------------------
__global__ __launch_bounds__(256) void biaffine_kernel(
    const float* __restrict__ U,
    const float* __restrict__ logit_bias,
    float* __restrict__ out)
{
    const int b  = blockIdx.z;
    const int i0 = blockIdx.y * 32;
    const int j0 = blockIdx.x * 16;

    __shared__ float sl[32][32];   // [h][i]
    __shared__ float sr[32][16];   // [h][j]
    __shared__ float su[32];

    const int tid = threadIdx.x;
    const int tx  = tid & 15;      // j (1 each)
    const int ty  = tid >> 4;      // i group (2 each)

    float acc[2] = {0.f, 0.f};

    for (int h0 = 0; h0 < HH; h0 += 32) {
        // sl: 32x32 floats = 256 float4 -> 1 per thread
        {
            int hk  = tid >> 3;             // 0..31
            int col = (tid & 7) << 2;       // 0..28
            *(float4*)&sl[hk][col] = *(const float4*)&g_dlt[(b * HH + h0 + hk) * LL + i0 + col];
        }
        // sr: 32x16 floats = 128 float4 -> first 128 threads
        if (tid < 128) {
            int hk  = tid >> 2;             // 0..31
            int col = (tid & 3) << 2;       // 0..12
            *(float4*)&sr[hk][col] = *(const float4*)&g_drt[(b * HH + h0 + hk) * LL + j0 + col];
        }
        if (tid < 32) su[tid] = U[h0 + tid];
        __syncthreads();

#pragma unroll
        for (int hk = 0; hk < 32; hk++) {
            float dl[2];
            *(float2*)dl = *(const float2*)&sl[hk][ty << 1];
            const float dr = sr[hk][tx];
            const float u  = su[hk];
            acc[0] = fmaf(u, tanh_fast(dl[0] + dr), acc[0]);
            acc[1] = fmaf(u, tanh_fast(dl[1] + dr), acc[1]);
        }
        __syncthreads();
    }

    const float lb = logit_bias[0];

#pragma unroll
    for (int a = 0; a < 2; a++) {
        const int i = i0 + (ty << 1) + a;
        const int j = j0 + tx;
        float x = acc[a] + lb;
        if (i == j) x -= 1e8f;

        const int m = i * (BB * LL) + b * LL + j;   // [L,B,L] flat index

        // mask_scores
        out[NTOT + m] = x;

        // p = sigmoid(x)
        const float p = 1.0f / (1.0f + expf(-x));

        // entropy = p*softplus(-x) + (1-p)*softplus(x)
        const float e  = expf(-fabsf(x));
        const float l1 = log1pf(e);
        const float sp_pos = fmaxf(x, 0.f) + l1;   // softplus(x)
        const float sp_neg = fmaxf(-x, 0.f) + l1;  // softplus(-x)
        out[2 * NTOT + m] = p * sp_neg + (1.0f - p) * sp_pos;

        // bernoulli sample, JAX partitionable threefry (key=42)
        const unsigned bits = threefry_bits_partitionable((unsigned)m);
        const float u01 = __uint_as_float((bits >> 9) | 0x3f800000u) - 1.0f;
        out[m] = (u01 < p) ? 1.0f : 0.0f;
    }
}

// ---------------------------------------------------------------------------
extern "C" void kernel_launch(void* const* d_in, const int* in_sizes, int n_in,
                              void* d_out, int out_size)
{
    const float* enc  = (const float*)d_in[0];
    const float* Wl   = (const float*)d_in[1];
    const float* Wr   = (const float*)d_in[2];
    const float* U    = (const float*)d_in[3];
    const float* bias = (const float*)d_in[4];
    float* out = (float*)d_out;

    dim3 g1(HH / 64, LL / 64, BB);   // 8 x 4 x 8 = 256 CTAs
    dual_gemm_kernel<<<g1, 256>>>(enc, Wl, Wr);

    dim3 g2(LL / 16, LL / 32, BB);   // 16 x 8 x 8 = 1024 CTAs
    biaffine_kernel<<<g2, 256>>>(U, bias, out);
}